// round 1
// baseline (speedup 1.0000x reference)
#include <cuda_runtime.h>
#include <math.h>

#define Bb 8
#define Nn 4096
#define DIM 768
#define HEADS 6
#define HD 128
#define QKVC 1536
#define NCHUNK 8
#define CHUNK (Nn/NCHUNK)   // 512
#define EPS 1e-12f

// ------------------ scratch (device globals: no allocs allowed) ------------------
__device__ float g_qkv[(size_t)Bb*Nn*QKVC];          // 201 MB
__device__ float g_nsum[Bb*QKVC];                    // column sum-of-squares
__device__ float g_inv[Bb*QKVC];                     // 1/max(norm,eps)
__device__ float g_P[NCHUNK][Bb*HEADS*HD*HD];        // attn partials, 25 MB
__device__ float g_attn[(size_t)Bb*HEADS*HD*HD];     // softmaxed attn, 3 MB
__device__ float g_tmp[(size_t)Bb*Nn*DIM];           // pre-projection output, 100 MB

// ------------------ generic 128x128x8 sgemm, 256 threads, 8x8 micro ------------------
template<int BIAS>
__global__ __launch_bounds__(256)
void sgemm128(const float* __restrict__ A, const float* __restrict__ Bm,
              const float* __restrict__ bias, float* __restrict__ C,
              int M, int Ncols, int K)
{
    __shared__ float As[8][128];
    __shared__ float Bs[8][128];
    const int m0 = blockIdx.y * 128, n0 = blockIdx.x * 128;
    const int tid = threadIdx.x;
    const int tx = tid & 15, ty = tid >> 4;

    float acc[8][8];
#pragma unroll
    for (int i = 0; i < 8; i++)
#pragma unroll
        for (int j = 0; j < 8; j++) acc[i][j] = 0.f;

    const int arow = tid >> 1, acol = (tid & 1) * 4;
    const int brow = tid >> 5, bcol = (tid & 31) * 4;
    const float* Ap = A + (size_t)(m0 + arow) * K + acol;
    const float* Bp = Bm + (size_t)brow * Ncols + n0 + bcol;

    for (int k0 = 0; k0 < K; k0 += 8) {
        float4 av = *(const float4*)(Ap + k0);
        As[acol + 0][arow] = av.x;
        As[acol + 1][arow] = av.y;
        As[acol + 2][arow] = av.z;
        As[acol + 3][arow] = av.w;
        float4 bv = *(const float4*)(Bp + (size_t)k0 * Ncols);
        *(float4*)&Bs[brow][bcol] = bv;
        __syncthreads();
#pragma unroll
        for (int k = 0; k < 8; k++) {
            float a[8], b[8];
#pragma unroll
            for (int i = 0; i < 8; i++) a[i] = As[k][ty * 8 + i];
#pragma unroll
            for (int j = 0; j < 8; j++) b[j] = Bs[k][tx * 8 + j];
#pragma unroll
            for (int i = 0; i < 8; i++)
#pragma unroll
                for (int j = 0; j < 8; j++) acc[i][j] += a[i] * b[j];
        }
        __syncthreads();
    }

#pragma unroll
    for (int i = 0; i < 8; i++) {
        size_t row = (size_t)(m0 + ty * 8 + i) * Ncols + n0 + tx * 8;
#pragma unroll
        for (int j = 0; j < 8; j += 4) {
            float4 o;
            o.x = acc[i][j + 0]; o.y = acc[i][j + 1];
            o.z = acc[i][j + 2]; o.w = acc[i][j + 3];
            if (BIAS) {
                o.x += bias[n0 + tx * 8 + j + 0];
                o.y += bias[n0 + tx * 8 + j + 1];
                o.z += bias[n0 + tx * 8 + j + 2];
                o.w += bias[n0 + tx * 8 + j + 3];
            }
            *(float4*)&C[row + j] = o;
        }
    }
}

// ------------------ zero helper ------------------
__global__ void zero_nsum() {
    int i = blockIdx.x * 256 + threadIdx.x;
    if (i < Bb * QKVC) g_nsum[i] = 0.f;
}

// ------------------ column sum-of-squares partials ------------------
__global__ __launch_bounds__(256)
void partial_norm()
{
    // grid (QKVC/256, NCHUNK, B)
    int col = blockIdx.x * 256 + threadIdx.x;
    int ch = blockIdx.y, b = blockIdx.z;
    const float* p = g_qkv + ((size_t)b * Nn + (size_t)ch * CHUNK) * QKVC + col;
    float s = 0.f;
    for (int n = 0; n < CHUNK; n++) {
        float v = p[(size_t)n * QKVC];
        s += v * v;
    }
    atomicAdd(&g_nsum[b * QKVC + col], s);
}

__global__ void inv_norm() {
    int i = blockIdx.x * 256 + threadIdx.x;
    if (i < Bb * QKVC) {
        float nr = sqrtf(g_nsum[i]);
        g_inv[i] = 1.f / fmaxf(nr, EPS);
    }
}

// ------------------ attn partials: per (h,b,chunk), full 128x128 over 512 tokens ------------------
__global__ __launch_bounds__(256)
void attn_partial()
{
    // grid (HEADS, B, NCHUNK)
    int h = blockIdx.x, b = blockIdx.y, ch = blockIdx.z;
    __shared__ float Qs[16][128];
    __shared__ float Ks[16][128];
    int tid = threadIdx.x;
    int tx = tid & 15, ty = tid >> 4;
    float acc[8][8];
#pragma unroll
    for (int i = 0; i < 8; i++)
#pragma unroll
        for (int j = 0; j < 8; j++) acc[i][j] = 0.f;

    const float* qbase = g_qkv + ((size_t)b * Nn + (size_t)ch * CHUNK) * QKVC + h * HD;
    const float* kbase = qbase + DIM;   // k slot is +768
    int lrow = tid >> 5;            // 0..7
    int lcol = (tid & 31) * 4;      // 0..124

    for (int n0 = 0; n0 < CHUNK; n0 += 16) {
#pragma unroll
        for (int p = 0; p < 2; p++) {
            int n = n0 + lrow + p * 8;
            float4 qv = *(const float4*)(qbase + (size_t)n * QKVC + lcol);
            *(float4*)&Qs[lrow + p * 8][lcol] = qv;
            float4 kv = *(const float4*)(kbase + (size_t)n * QKVC + lcol);
            *(float4*)&Ks[lrow + p * 8][lcol] = kv;
        }
        __syncthreads();
#pragma unroll
        for (int n = 0; n < 16; n++) {
            float a[8], bv[8];
#pragma unroll
            for (int i = 0; i < 8; i++) a[i] = Qs[n][ty * 8 + i];
#pragma unroll
            for (int j = 0; j < 8; j++) bv[j] = Ks[n][tx * 8 + j];
#pragma unroll
            for (int i = 0; i < 8; i++)
#pragma unroll
                for (int j = 0; j < 8; j++) acc[i][j] += a[i] * bv[j];
        }
        __syncthreads();
    }

    float* Pp = &g_P[ch][(size_t)(b * HEADS + h) * HD * HD];
#pragma unroll
    for (int i = 0; i < 8; i++) {
        size_t row = (size_t)(ty * 8 + i) * HD + tx * 8;
#pragma unroll
        for (int j = 0; j < 8; j += 4) {
            float4 o;
            o.x = acc[i][j + 0]; o.y = acc[i][j + 1];
            o.z = acc[i][j + 2]; o.w = acc[i][j + 3];
            *(float4*)&Pp[row + j] = o;
        }
    }
}

// ------------------ sum partials + scale + softmax (one block per (b,h,c) row) ------------------
__global__ __launch_bounds__(128)
void softmax_rows(const float* __restrict__ temperature)
{
    // grid (HD, HEADS, B), block 128 (thread = d)
    int c = blockIdx.x, h = blockIdx.y, b = blockIdx.z;
    int d = threadIdx.x;
    size_t off = ((size_t)(b * HEADS + h) * HD + c) * HD + d;

    float s = 0.f;
#pragma unroll
    for (int ch = 0; ch < NCHUNK; ch++) s += g_P[ch][off];

    float scale = g_inv[b * QKVC + h * HD + c] *
                  g_inv[b * QKVC + DIM + h * HD + d] *
                  temperature[h];
    float val = s * scale;

    __shared__ float red[128];
    red[d] = val;
    __syncthreads();
    for (int o = 64; o >= 1; o >>= 1) {
        if (d < o) red[d] = fmaxf(red[d], red[d + o]);
        __syncthreads();
    }
    float mx = red[0];
    __syncthreads();
    float e = expf(val - mx);
    red[d] = e;
    __syncthreads();
    for (int o = 64; o >= 1; o >>= 1) {
        if (d < o) red[d] += red[d + o];
        __syncthreads();
    }
    float inv = 1.f / red[0];
    g_attn[off] = e * inv;
}

// ------------------ out_tmp[b,n,h*128+c] = sum_d attn[b,h,c,d] * y[b,n,h*128+d] ------------------
__global__ __launch_bounds__(256)
void av_kernel(const float* __restrict__ y)
{
    // grid (N/32, HEADS, B), block 256
    int nblk = blockIdx.x, h = blockIdx.y, b = blockIdx.z;
    int tid = threadIdx.x;
    int nl = tid >> 3;          // 0..31 (token row within tile)
    int cb = (tid & 7) * 16;    // 16 output channels per thread

    __shared__ float Ys[32][36];
    __shared__ float At[32][128];   // At[d][c]

    float acc[16];
#pragma unroll
    for (int j = 0; j < 16; j++) acc[j] = 0.f;

    const float* attnp = g_attn + (size_t)(b * HEADS + h) * HD * HD;
    const float* ybase = y + ((size_t)b * Nn + (size_t)nblk * 32) * DIM + h * HD;

    for (int d0 = 0; d0 < HD; d0 += 32) {
        // Y chunk [32 n][32 d]
        {
            int r = tid >> 3, c4 = (tid & 7) * 4;
            float4 yv = *(const float4*)(ybase + (size_t)r * DIM + d0 + c4);
            *(float4*)&Ys[r][c4] = yv;
        }
        // attn chunk transposed: At[d][c], d in [d0,d0+32)
#pragma unroll
        for (int pass = 0; pass < 4; pass++) {
            int c = pass * 32 + (tid >> 3);
            int dl = (tid & 7) * 4;
            float4 a = *(const float4*)(attnp + (size_t)c * HD + d0 + dl);
            At[dl + 0][c] = a.x;
            At[dl + 1][c] = a.y;
            At[dl + 2][c] = a.z;
            At[dl + 3][c] = a.w;
        }
        __syncthreads();
#pragma unroll
        for (int dd = 0; dd < 32; dd++) {
            float yv = Ys[nl][dd];
#pragma unroll
            for (int j = 0; j < 16; j++) acc[j] += yv * At[dd][cb + j];
        }
        __syncthreads();
    }

    float* op = g_tmp + ((size_t)b * Nn + (size_t)nblk * 32 + nl) * DIM + h * HD + cb;
#pragma unroll
    for (int j = 0; j < 16; j += 4) {
        float4 o;
        o.x = acc[j + 0]; o.y = acc[j + 1]; o.z = acc[j + 2]; o.w = acc[j + 3];
        *(float4*)(op + j) = o;
    }
}

// ------------------ launch ------------------
extern "C" void kernel_launch(void* const* d_in, const int* in_sizes, int n_in,
                              void* d_out, int out_size)
{
    const float* x     = (const float*)d_in[0];
    const float* y     = (const float*)d_in[1];
    const float* W_qkv = (const float*)d_in[2];
    const float* temp  = (const float*)d_in[3];
    const float* W_prj = (const float*)d_in[4];
    const float* b_prj = (const float*)d_in[5];
    float* out = (float*)d_out;

    float *qkv_p, *tmp_p;
    cudaGetSymbolAddress((void**)&qkv_p, g_qkv);
    cudaGetSymbolAddress((void**)&tmp_p, g_tmp);

    // 1. qkv = x @ W_qkv   [32768 x 768] @ [768 x 1536]
    sgemm128<0><<<dim3(QKVC / 128, (Bb * Nn) / 128), 256>>>(
        x, W_qkv, nullptr, qkv_p, Bb * Nn, QKVC, DIM);

    // 2. column norms of q,k over token dim
    zero_nsum<<<(Bb * QKVC + 255) / 256, 256>>>();
    partial_norm<<<dim3(QKVC / 256, NCHUNK, Bb), 256>>>();
    inv_norm<<<(Bb * QKVC + 255) / 256, 256>>>();

    // 3. attn partials per (h, b, chunk)
    attn_partial<<<dim3(HEADS, Bb, NCHUNK), 256>>>();

    // 4. sum + scale + softmax
    softmax_rows<<<dim3(HD, HEADS, Bb), 128>>>(temp);

    // 5. out_tmp = attn @ v
    av_kernel<<<dim3(Nn / 32, HEADS, Bb), 256>>>(y);

    // 6. out = out_tmp @ W_proj + b
    sgemm128<1><<<dim3(DIM / 128, (Bb * Nn) / 128), 256>>>(
        tmp_p, W_prj, b_prj, out, Bb * Nn, DIM, DIM);
}

// round 4
// speedup vs baseline: 1.7465x; 1.7465x over previous
#include <cuda_runtime.h>
#include <math.h>
#include <stdint.h>

#define Bb 8
#define Nn 4096
#define DIM 768
#define HEADS 6
#define HD 128
#define QKVC 1536
#define NCHUNK 8
#define CHUNK (Nn/NCHUNK)   // 512
#define EPS 1e-12f

// ------------------ scratch (device globals: no allocs allowed) ------------------
__device__ float g_qkv[(size_t)Bb*Nn*QKVC];          // 201 MB
__device__ float g_nsum[Bb*QKVC];                    // column sum-of-squares
__device__ float g_inv[Bb*QKVC];                     // 1/max(norm,eps)
__device__ float g_P[NCHUNK][Bb*HEADS*HD*HD];        // attn partials, 25 MB
__device__ float g_attn[(size_t)Bb*HEADS*HD*HD];     // softmaxed attn, 3 MB
__device__ float g_tmp[(size_t)Bb*Nn*DIM];           // pre-projection output, 100 MB

// ------------------ tf32 helpers ------------------
__device__ __forceinline__ uint32_t f2tf32(float x) {
    uint32_t r;
    asm("cvt.rna.tf32.f32 %0, %1;" : "=r"(r) : "f"(x));
    return r;
}

// ------------------ tf32 tensor-core GEMM: 128x128x32 tile, 256 thr ------------------
// C[M,N] = A[M,K] @ B[K,N] (+bias), all row-major fp32, compute tf32.
template<int BIAS>
__global__ __launch_bounds__(256)
void tf32gemm(const float* __restrict__ A, const float* __restrict__ Bm,
              const float* __restrict__ bias, float* __restrict__ C,
              int M, int N, int K)
{
    // A stride 44: bank = (12*m + k) mod 32 -> conflict-free frags, float4-aligned.
    // B stride 168: bank = (8*k + n) mod 32 -> conflict-free frags, float4-aligned.
    __shared__ uint32_t As[128][44];
    __shared__ uint32_t Bs[32][168];

    const int tid  = threadIdx.x;
    const int m0   = blockIdx.y * 128, n0 = blockIdx.x * 128;
    const int warp = tid >> 5, lane = tid & 31;
    const int wm   = warp >> 1, wn = warp & 1;     // warp grid 4(m) x 2(n)
    const int g    = lane >> 2, tg = lane & 3;

    float acc[2][8][4];
#pragma unroll
    for (int mt = 0; mt < 2; mt++)
#pragma unroll
        for (int nt = 0; nt < 8; nt++)
#pragma unroll
            for (int i = 0; i < 4; i++) acc[mt][nt][i] = 0.f;

    const int arow = tid >> 3, acol = (tid & 7) * 4;   // A tile 128x32: 4 rows/thread stride 32
    const int brow = tid >> 5, bcol = (tid & 31) * 4;  // B tile 32x128: 4 rows/thread stride 8
    const float* Ap = A + (size_t)(m0 + arow) * K + acol;
    const float* Bp = Bm + (size_t)brow * N + n0 + bcol;

    float4 ar[4], br[4];
#pragma unroll
    for (int i = 0; i < 4; i++) ar[i] = *(const float4*)(Ap + (size_t)(i * 32) * K);
#pragma unroll
    for (int i = 0; i < 4; i++) br[i] = *(const float4*)(Bp + (size_t)(i * 8) * N);

    const int KT = K / 32;
    for (int kt = 0; kt < KT; kt++) {
        // convert + store current tile to smem
#pragma unroll
        for (int i = 0; i < 4; i++) {
            uint4 w;
            w.x = f2tf32(ar[i].x); w.y = f2tf32(ar[i].y);
            w.z = f2tf32(ar[i].z); w.w = f2tf32(ar[i].w);
            *(uint4*)&As[arow + i * 32][acol] = w;
        }
#pragma unroll
        for (int i = 0; i < 4; i++) {
            uint4 w;
            w.x = f2tf32(br[i].x); w.y = f2tf32(br[i].y);
            w.z = f2tf32(br[i].z); w.w = f2tf32(br[i].w);
            *(uint4*)&Bs[brow + i * 8][bcol] = w;
        }
        __syncthreads();

        // prefetch next tile into registers
        if (kt + 1 < KT) {
            const float* Ap2 = Ap + (kt + 1) * 32;
            const float* Bp2 = Bp + (size_t)(kt + 1) * 32 * N;
#pragma unroll
            for (int i = 0; i < 4; i++) ar[i] = *(const float4*)(Ap2 + (size_t)(i * 32) * K);
#pragma unroll
            for (int i = 0; i < 4; i++) br[i] = *(const float4*)(Bp2 + (size_t)(i * 8) * N);
        }

        // compute 32 k-steps (4 x k8)
#pragma unroll
        for (int ks = 0; ks < 4; ks++) {
            const int kb = ks * 8;
            uint32_t af[2][4];
#pragma unroll
            for (int mt = 0; mt < 2; mt++) {
                int mr = wm * 32 + mt * 16 + g;
                af[mt][0] = As[mr][kb + tg];
                af[mt][1] = As[mr + 8][kb + tg];
                af[mt][2] = As[mr][kb + tg + 4];
                af[mt][3] = As[mr + 8][kb + tg + 4];
            }
            uint32_t bf[8][2];
#pragma unroll
            for (int nt = 0; nt < 8; nt++) {
                int nc = wn * 64 + nt * 8 + g;
                bf[nt][0] = Bs[kb + tg][nc];
                bf[nt][1] = Bs[kb + tg + 4][nc];
            }
#pragma unroll
            for (int mt = 0; mt < 2; mt++)
#pragma unroll
                for (int nt = 0; nt < 8; nt++) {
                    float* c = acc[mt][nt];
                    asm volatile(
                        "mma.sync.aligned.m16n8k8.row.col.f32.tf32.tf32.f32 "
                        "{%0,%1,%2,%3},{%4,%5,%6,%7},{%8,%9},{%0,%1,%2,%3};"
                        : "+f"(c[0]), "+f"(c[1]), "+f"(c[2]), "+f"(c[3])
                        : "r"(af[mt][0]), "r"(af[mt][1]), "r"(af[mt][2]), "r"(af[mt][3]),
                          "r"(bf[nt][0]), "r"(bf[nt][1]));
                }
        }
        __syncthreads();
    }

    // epilogue
#pragma unroll
    for (int mt = 0; mt < 2; mt++) {
#pragma unroll
        for (int half = 0; half < 2; half++) {
            int row = m0 + wm * 32 + mt * 16 + g + half * 8;
#pragma unroll
            for (int nt = 0; nt < 8; nt++) {
                int col = n0 + wn * 64 + nt * 8 + tg * 2;
                float2 o;
                o.x = acc[mt][nt][half * 2 + 0];
                o.y = acc[mt][nt][half * 2 + 1];
                if (BIAS) { o.x += bias[col]; o.y += bias[col + 1]; }
                *(float2*)&C[(size_t)row * N + col] = o;
            }
        }
    }
}

// ------------------ zero helper ------------------
__global__ void zero_nsum() {
    int i = blockIdx.x * 256 + threadIdx.x;
    if (i < Bb * QKVC) g_nsum[i] = 0.f;
}

// ------------------ column sum-of-squares partials ------------------
__global__ __launch_bounds__(256)
void partial_norm()
{
    int col = blockIdx.x * 256 + threadIdx.x;
    int ch = blockIdx.y, b = blockIdx.z;
    const float* p = g_qkv + ((size_t)b * Nn + (size_t)ch * CHUNK) * QKVC + col;
    float s = 0.f;
    for (int n = 0; n < CHUNK; n++) {
        float v = p[(size_t)n * QKVC];
        s += v * v;
    }
    atomicAdd(&g_nsum[b * QKVC + col], s);
}

__global__ void inv_norm() {
    int i = blockIdx.x * 256 + threadIdx.x;
    if (i < Bb * QKVC) {
        float nr = sqrtf(g_nsum[i]);
        g_inv[i] = 1.f / fmaxf(nr, EPS);
    }
}

// ------------------ attn partials: per (h,b,chunk), 128x128 over 512 tokens ------------------
__global__ __launch_bounds__(256)
void attn_partial()
{
    int h = blockIdx.x, b = blockIdx.y, ch = blockIdx.z;
    __shared__ float Qs[16][128];
    __shared__ float Ks[16][128];
    int tid = threadIdx.x;
    int tx = tid & 15, ty = tid >> 4;
    float acc[8][8];
#pragma unroll
    for (int i = 0; i < 8; i++)
#pragma unroll
        for (int j = 0; j < 8; j++) acc[i][j] = 0.f;

    const float* qbase = g_qkv + ((size_t)b * Nn + (size_t)ch * CHUNK) * QKVC + h * HD;
    const float* kbase = qbase + DIM;
    int lrow = tid >> 5;
    int lcol = (tid & 31) * 4;

    for (int n0 = 0; n0 < CHUNK; n0 += 16) {
#pragma unroll
        for (int p = 0; p < 2; p++) {
            int n = n0 + lrow + p * 8;
            float4 qv = *(const float4*)(qbase + (size_t)n * QKVC + lcol);
            *(float4*)&Qs[lrow + p * 8][lcol] = qv;
            float4 kv = *(const float4*)(kbase + (size_t)n * QKVC + lcol);
            *(float4*)&Ks[lrow + p * 8][lcol] = kv;
        }
        __syncthreads();
#pragma unroll
        for (int n = 0; n < 16; n++) {
            float a[8], bv[8];
#pragma unroll
            for (int i = 0; i < 8; i++) a[i] = Qs[n][ty * 8 + i];
#pragma unroll
            for (int j = 0; j < 8; j++) bv[j] = Ks[n][tx * 8 + j];
#pragma unroll
            for (int i = 0; i < 8; i++)
#pragma unroll
                for (int j = 0; j < 8; j++) acc[i][j] += a[i] * bv[j];
        }
        __syncthreads();
    }

    float* Pp = &g_P[ch][(size_t)(b * HEADS + h) * HD * HD];
#pragma unroll
    for (int i = 0; i < 8; i++) {
        size_t row = (size_t)(ty * 8 + i) * HD + tx * 8;
#pragma unroll
        for (int j = 0; j < 8; j += 4) {
            float4 o;
            o.x = acc[i][j + 0]; o.y = acc[i][j + 1];
            o.z = acc[i][j + 2]; o.w = acc[i][j + 3];
            *(float4*)&Pp[row + j] = o;
        }
    }
}

// ------------------ sum partials + scale + softmax ------------------
__global__ __launch_bounds__(128)
void softmax_rows(const float* __restrict__ temperature)
{
    int c = blockIdx.x, h = blockIdx.y, b = blockIdx.z;
    int d = threadIdx.x;
    size_t off = ((size_t)(b * HEADS + h) * HD + c) * HD + d;

    float s = 0.f;
#pragma unroll
    for (int ch = 0; ch < NCHUNK; ch++) s += g_P[ch][off];

    float scale = g_inv[b * QKVC + h * HD + c] *
                  g_inv[b * QKVC + DIM + h * HD + d] *
                  temperature[h];
    float val = s * scale;

    __shared__ float red[128];
    red[d] = val;
    __syncthreads();
    for (int o = 64; o >= 1; o >>= 1) {
        if (d < o) red[d] = fmaxf(red[d], red[d + o]);
        __syncthreads();
    }
    float mx = red[0];
    __syncthreads();
    float e = expf(val - mx);
    red[d] = e;
    __syncthreads();
    for (int o = 64; o >= 1; o >>= 1) {
        if (d < o) red[d] += red[d + o];
        __syncthreads();
    }
    float inv = 1.f / red[0];
    g_attn[off] = e * inv;
}

// ------------------ out_tmp = attn @ v ------------------
__global__ __launch_bounds__(256)
void av_kernel(const float* __restrict__ y)
{
    int nblk = blockIdx.x, h = blockIdx.y, b = blockIdx.z;
    int tid = threadIdx.x;
    int nl = tid >> 3;
    int cb = (tid & 7) * 16;

    __shared__ float Ys[32][36];
    __shared__ float At[32][128];

    float acc[16];
#pragma unroll
    for (int j = 0; j < 16; j++) acc[j] = 0.f;

    const float* attnp = g_attn + (size_t)(b * HEADS + h) * HD * HD;
    const float* ybase = y + ((size_t)b * Nn + (size_t)nblk * 32) * DIM + h * HD;

    for (int d0 = 0; d0 < HD; d0 += 32) {
        {
            int r = tid >> 3, c4 = (tid & 7) * 4;
            float4 yv = *(const float4*)(ybase + (size_t)r * DIM + d0 + c4);
            *(float4*)&Ys[r][c4] = yv;
        }
#pragma unroll
        for (int pass = 0; pass < 4; pass++) {
            int c = pass * 32 + (tid >> 3);
            int dl = (tid & 7) * 4;
            float4 a = *(const float4*)(attnp + (size_t)c * HD + d0 + dl);
            At[dl + 0][c] = a.x;
            At[dl + 1][c] = a.y;
            At[dl + 2][c] = a.z;
            At[dl + 3][c] = a.w;
        }
        __syncthreads();
#pragma unroll
        for (int dd = 0; dd < 32; dd++) {
            float yv = Ys[nl][dd];
#pragma unroll
            for (int j = 0; j < 16; j++) acc[j] += yv * At[dd][cb + j];
        }
        __syncthreads();
    }

    float* op = g_tmp + ((size_t)b * Nn + (size_t)nblk * 32 + nl) * DIM + h * HD + cb;
#pragma unroll
    for (int j = 0; j < 16; j += 4) {
        float4 o;
        o.x = acc[j + 0]; o.y = acc[j + 1]; o.z = acc[j + 2]; o.w = acc[j + 3];
        *(float4*)(op + j) = o;
    }
}

// ------------------ launch ------------------
extern "C" void kernel_launch(void* const* d_in, const int* in_sizes, int n_in,
                              void* d_out, int out_size)
{
    const float* x     = (const float*)d_in[0];
    const float* y     = (const float*)d_in[1];
    const float* W_qkv = (const float*)d_in[2];
    const float* temp  = (const float*)d_in[3];
    const float* W_prj = (const float*)d_in[4];
    const float* b_prj = (const float*)d_in[5];
    float* out = (float*)d_out;

    float *qkv_p, *tmp_p;
    cudaGetSymbolAddress((void**)&qkv_p, g_qkv);
    cudaGetSymbolAddress((void**)&tmp_p, g_tmp);

    // 1. qkv = x @ W_qkv   [32768 x 768] @ [768 x 1536] (tf32 tensor cores)
    tf32gemm<0><<<dim3(QKVC / 128, (Bb * Nn) / 128), 256>>>(
        x, W_qkv, nullptr, qkv_p, Bb * Nn, QKVC, DIM);

    // 2. column norms of q,k over token dim
    zero_nsum<<<(Bb * QKVC + 255) / 256, 256>>>();
    partial_norm<<<dim3(QKVC / 256, NCHUNK, Bb), 256>>>();
    inv_norm<<<(Bb * QKVC + 255) / 256, 256>>>();

    // 3. attn partials per (h, b, chunk)
    attn_partial<<<dim3(HEADS, Bb, NCHUNK), 256>>>();

    // 4. sum + scale + softmax
    softmax_rows<<<dim3(HD, HEADS, Bb), 128>>>(temp);

    // 5. out_tmp = attn @ v
    av_kernel<<<dim3(Nn / 32, HEADS, Bb), 256>>>(y);

    // 6. out = out_tmp @ W_proj + b (tf32 tensor cores)
    tf32gemm<1><<<dim3(DIM / 128, (Bb * Nn) / 128), 256>>>(
        tmp_p, W_prj, b_prj, out, Bb * Nn, DIM, DIM);
}